// round 1
// baseline (speedup 1.0000x reference)
#include <cuda_runtime.h>
#include <math.h>

// Problem constants (fixed by the reference)
#define BB   8
#define CC   3
#define HH   512
#define WW   512
#define HW   (HH * WW)        // 262144 = 2^18
#define NPIX (BB * HW)        // 2097152

#define GRID 1024
#define TPB  256

// Scratch for partial reductions (no device allocation allowed)
__device__ double g_psum[GRID];
__device__ float  g_pmax[GRID];

__global__ __launch_bounds__(TPB) void map_loss_main(
    const float* __restrict__ target,
    const float* __restrict__ mu,
    const float* __restrict__ sy)
{
    double lsum = 0.0;
    float  lmax = -3.0e38f;

    const int stride = GRID * TPB;
    for (int i = blockIdx.x * TPB + threadIdx.x; i < NPIX; i += stride) {
        const int b  = i >> 18;          // i / HW
        const int hw = i & (HW - 1);     // i % HW
        const int base = b * (CC * HW) + hw;

        // Residual T = target - mu, channels strided by HW (coalesced per channel)
        const float t0 = target[base]          - mu[base];
        const float t1 = target[base + HW]     - mu[base + HW];
        const float t2 = target[base + 2 * HW] - mu[base + 2 * HW];

        // sigma_y: 9 contiguous floats per pixel, symmetric -> 6 unique
        const float* s = sy + (size_t)i * 9;
        const float a  = s[0];
        const float bq = s[1];
        const float c  = s[2];
        const float d  = s[4];
        const float e  = s[5];
        const float f  = s[8];

        // Adjugate of symmetric 3x3 (upper triangle) + determinant
        const float A00 = d * f - e * e;
        const float A01 = c * e - bq * f;
        const float A02 = bq * e - c * d;
        const float A11 = a * f - c * c;
        const float A12 = bq * c - a * e;
        const float A22 = a * d - bq * bq;
        const float det = a * A00 + bq * A01 + c * A02;

        // quad = T^t adj(Sigma) T
        const float quad =
            t0 * t0 * A00 + t1 * t1 * A11 + t2 * t2 * A22 +
            2.0f * (t0 * t1 * A01 + t0 * t2 * A02 + t1 * t2 * A12);

        const float q  = 0.5f * quad / det;   // t1 term of reference
        const float ld = 0.5f * logf(det);    // t2 term

        lsum += (double)(q + ld);
        lmax  = fmaxf(lmax, q);
    }

    // Block reduction
    __shared__ double ssum[TPB];
    __shared__ float  smax[TPB];
    ssum[threadIdx.x] = lsum;
    smax[threadIdx.x] = lmax;
    __syncthreads();
    #pragma unroll
    for (int off = TPB / 2; off > 0; off >>= 1) {
        if (threadIdx.x < off) {
            ssum[threadIdx.x] += ssum[threadIdx.x + off];
            smax[threadIdx.x] = fmaxf(smax[threadIdx.x], smax[threadIdx.x + off]);
        }
        __syncthreads();
    }
    if (threadIdx.x == 0) {
        g_psum[blockIdx.x] = ssum[0];
        g_pmax[blockIdx.x] = smax[0];
    }
}

__global__ __launch_bounds__(GRID) void map_loss_final(float* __restrict__ out)
{
    __shared__ double ssum[GRID];
    __shared__ float  smax[GRID];
    const int t = threadIdx.x;
    ssum[t] = g_psum[t];
    smax[t] = g_pmax[t];
    __syncthreads();
    #pragma unroll
    for (int off = GRID / 2; off > 0; off >>= 1) {
        if (t < off) {
            ssum[t] += ssum[t + off];
            smax[t] = fmaxf(smax[t], smax[t + off]);
        }
        __syncthreads();
    }
    if (t == 0) {
        float loss = (float)(ssum[0] / (double)NPIX);
        if (smax[0] > 1e8f) loss = 0.0f;
        out[0] = loss;
    }
}

extern "C" void kernel_launch(void* const* d_in, const int* in_sizes, int n_in,
                              void* d_out, int out_size)
{
    // metadata order: target, mu, sigma_mu, sigma_n, sigma_y
    const float* target = (const float*)d_in[0];
    const float* mu     = (const float*)d_in[1];
    // d_in[2] (sigma_mu) and d_in[3] (sigma_n) are unused by the reference.
    const float* sy     = (const float*)d_in[4];
    float* out = (float*)d_out;

    map_loss_main<<<GRID, TPB>>>(target, mu, sy);
    map_loss_final<<<1, GRID>>>(out);
}